// round 4
// baseline (speedup 1.0000x reference)
#include <cuda_runtime.h>
#include <math.h>

#define N_NODES 100000
#define N_EDGES 1600000
#define D 128
#define NLAYER 3
#define LN_EPS 1e-5f

// ---------------- scratch (static __device__ — no allocation allowed) ----------------
// NOTE: these are referenced ONLY inside device code. Passing a __device__
// symbol as a kernel argument from host code silently binds the host shadow
// address (ATS makes it "work") — that was the Round-1/2 bug.
__device__ float g_h[N_NODES * D];     // current node features
__device__ float g_hsum[N_NODES * D];  // jumping-knowledge sum
__device__ float g_z[N_NODES * D];     // GIN pre-MLP features / final LN output
__device__ float g_z1[N_NODES * D];    // hidden after first MLP layer
__device__ int g_deg[N_NODES];
__device__ int g_off[N_NODES];
__device__ int g_cur[N_NODES];
__device__ int g_col[N_EDGES];
__device__ int g_bsum[128];

// ---------------- init ----------------
__global__ void k_init(const float* __restrict__ x) {
    int i = blockIdx.x * blockDim.x + threadIdx.x;
    if (i < N_NODES * D) {
        g_h[i] = x[i];
        g_hsum[i] = 0.0f;
    }
}

__global__ void k_zero_deg() {
    int i = blockIdx.x * blockDim.x + threadIdx.x;
    if (i < N_NODES) g_deg[i] = 0;
}

// ---------------- CSR build (bucket by dst, store src) ----------------
__global__ void k_hist(const int* __restrict__ dst) {
    int e = blockIdx.x * blockDim.x + threadIdx.x;
    if (e < N_EDGES) atomicAdd(&g_deg[dst[e]], 1);
}

__global__ void k_scan_local() {
    __shared__ int s[1024];
    int i = blockIdx.x * 1024 + threadIdx.x;
    int v = (i < N_NODES) ? g_deg[i] : 0;
    s[threadIdx.x] = v;
    __syncthreads();
#pragma unroll
    for (int off = 1; off < 1024; off <<= 1) {
        int t = (threadIdx.x >= off) ? s[threadIdx.x - off] : 0;
        __syncthreads();
        s[threadIdx.x] += t;
        __syncthreads();
    }
    if (i < N_NODES) g_off[i] = s[threadIdx.x] - v;  // exclusive
    if (threadIdx.x == 1023) g_bsum[blockIdx.x] = s[1023];
}

__global__ void k_scan_top(int nblk) {
    if (threadIdx.x == 0 && blockIdx.x == 0) {
        int run = 0;
        for (int b = 0; b < nblk; b++) {
            int t = g_bsum[b];
            g_bsum[b] = run;
            run += t;
        }
    }
}

__global__ void k_scan_add() {
    int i = blockIdx.x * blockDim.x + threadIdx.x;
    if (i < N_NODES) {
        int o = g_off[i] + g_bsum[i >> 10];
        g_off[i] = o;
        g_cur[i] = o;
    }
}

__global__ void k_scatter(const int* __restrict__ src, const int* __restrict__ dst) {
    int e = blockIdx.x * blockDim.x + threadIdx.x;
    if (e < N_EDGES) {
        int d = dst[e];
        int p = atomicAdd(&g_cur[d], 1);
        g_col[p] = src[e];
    }
}

// ---------------- aggregation: z[n] = (1+eps)*h[n] + sum_{nbr in CSR[n]} h[nbr] ----------------
__global__ __launch_bounds__(128) void k_agg(const float* __restrict__ eps, int layer) {
    __shared__ int s_col[128];
    int n = blockIdx.x;
    int d = threadIdx.x;
    int beg = g_off[n];
    int cnt = g_deg[n];
    float acc = (1.0f + eps[layer]) * g_h[(size_t)n * D + d];
    for (int base = 0; base < cnt; base += 128) {
        int m = min(128, cnt - base);
        if (d < m) s_col[d] = g_col[beg + base + d];
        __syncthreads();
#pragma unroll 4
        for (int j = 0; j < m; j++) {
            acc += __ldg(&g_h[(size_t)s_col[j] * D + d]);
        }
        __syncthreads();
    }
    g_z[(size_t)n * D + d] = acc;
}

// ---------------- GEMM core: C = A(M x 128) * B(128 x 128), block tile 128x128 ----------------
// 256 threads, 8x8 microtile per thread. B fully staged in smem; A in BK=16 slabs.
#define BM 128
#define BK 16

__device__ __forceinline__ void gemm_mainloop(const float* __restrict__ A,
                                              const float* __restrict__ B,
                                              float* Bs, float* As,
                                              float acc[8][8], int bm) {
    int tid = threadIdx.x;
    // load B fully: 16384 floats = 4096 float4 / 256 threads = 16 each
    {
        const float4* Bg = (const float4*)B;
        float4* Bs4 = (float4*)Bs;
#pragma unroll
        for (int i = 0; i < 16; i++) Bs4[tid + i * 256] = Bg[tid + i * 256];
    }
    int tr = (tid >> 4) * 8;
    int tc = (tid & 15) * 8;
    for (int k0 = 0; k0 < 128; k0 += BK) {
        __syncthreads();
        // load A slab [128 rows x 16 k] transposed into As[kk][m]
#pragma unroll
        for (int it = 0; it < 2; it++) {
            int idx = tid * 2 + it;
            int m = idx >> 2, q = idx & 3;
            int gm = bm + m;
            float4 v = make_float4(0.f, 0.f, 0.f, 0.f);
            if (gm < N_NODES) v = *(const float4*)(A + (size_t)gm * 128 + k0 + q * 4);
            As[(q * 4 + 0) * 128 + m] = v.x;
            As[(q * 4 + 1) * 128 + m] = v.y;
            As[(q * 4 + 2) * 128 + m] = v.z;
            As[(q * 4 + 3) * 128 + m] = v.w;
        }
        __syncthreads();
#pragma unroll
        for (int kk = 0; kk < BK; kk++) {
            float ar[8], br[8];
            *(float4*)&ar[0] = *(float4*)&As[kk * 128 + tr];
            *(float4*)&ar[4] = *(float4*)&As[kk * 128 + tr + 4];
            *(float4*)&br[0] = *(float4*)&Bs[(k0 + kk) * 128 + tc];
            *(float4*)&br[4] = *(float4*)&Bs[(k0 + kk) * 128 + tc + 4];
#pragma unroll
            for (int i = 0; i < 8; i++)
#pragma unroll
                for (int j = 0; j < 8; j++) acc[i][j] = fmaf(ar[i], br[j], acc[i][j]);
        }
    }
}

// GEMM + bias + ReLU: g_z1 = relu(g_z @ B + bias)
__global__ __launch_bounds__(256) void k_gemm_relu(const float* __restrict__ B,
                                                   const float* __restrict__ bias) {
    extern __shared__ float sm[];
    float* Bs = sm;
    float* As = sm + 128 * 128;
    float acc[8][8] = {};
    int bm = blockIdx.x * BM;
    gemm_mainloop(g_z, B, Bs, As, acc, bm);
    int tid = threadIdx.x;
    int tr = (tid >> 4) * 8;
    int tc = (tid & 15) * 8;
    float bz[8];
#pragma unroll
    for (int j = 0; j < 8; j++) bz[j] = __ldg(&bias[tc + j]);
#pragma unroll
    for (int i = 0; i < 8; i++) {
        int gm = bm + tr + i;
        if (gm < N_NODES) {
            float4 o0, o1;
            o0.x = fmaxf(acc[i][0] + bz[0], 0.f);
            o0.y = fmaxf(acc[i][1] + bz[1], 0.f);
            o0.z = fmaxf(acc[i][2] + bz[2], 0.f);
            o0.w = fmaxf(acc[i][3] + bz[3], 0.f);
            o1.x = fmaxf(acc[i][4] + bz[4], 0.f);
            o1.y = fmaxf(acc[i][5] + bz[5], 0.f);
            o1.z = fmaxf(acc[i][6] + bz[6], 0.f);
            o1.w = fmaxf(acc[i][7] + bz[7], 0.f);
            *(float4*)(g_z1 + (size_t)gm * 128 + tc) = o0;
            *(float4*)(g_z1 + (size_t)gm * 128 + tc + 4) = o1;
        }
    }
}

// GEMM + bias: out = g_z @ B + bias  (final projection, writes d_out)
__global__ __launch_bounds__(256) void k_gemm_bias(const float* __restrict__ B,
                                                   const float* __restrict__ bias,
                                                   float* __restrict__ out) {
    extern __shared__ float sm[];
    float* Bs = sm;
    float* As = sm + 128 * 128;
    float acc[8][8] = {};
    int bm = blockIdx.x * BM;
    gemm_mainloop(g_z, B, Bs, As, acc, bm);
    int tid = threadIdx.x;
    int tr = (tid >> 4) * 8;
    int tc = (tid & 15) * 8;
    float bz[8];
#pragma unroll
    for (int j = 0; j < 8; j++) bz[j] = __ldg(&bias[tc + j]);
#pragma unroll
    for (int i = 0; i < 8; i++) {
        int gm = bm + tr + i;
        if (gm < N_NODES) {
            float4 o0, o1;
            o0.x = acc[i][0] + bz[0];
            o0.y = acc[i][1] + bz[1];
            o0.z = acc[i][2] + bz[2];
            o0.w = acc[i][3] + bz[3];
            o1.x = acc[i][4] + bz[4];
            o1.y = acc[i][5] + bz[5];
            o1.z = acc[i][6] + bz[6];
            o1.w = acc[i][7] + bz[7];
            *(float4*)(out + (size_t)gm * 128 + tc) = o0;
            *(float4*)(out + (size_t)gm * 128 + tc + 4) = o1;
        }
    }
}

// GEMM + bias + LayerNorm + exact GELU + residual(g_h) + g_hsum accumulate.
// A = g_z1. Block tile covers full rows (128 cols) so LN is done in-block.
__global__ __launch_bounds__(256) void k_gemm_ln_gelu_res(const float* __restrict__ B,
                                                          const float* __restrict__ bias,
                                                          const float* __restrict__ lng,
                                                          const float* __restrict__ lnb) {
    extern __shared__ float sm[];
    float* Bs = sm;                    // 16384 floats — reused as C tile in epilogue
    float* As = sm + 128 * 128;        // 2048
    float* red = As + 2048;            // 256 (partial sums)
    float* red2 = red + 256;           // 256 (partial sumsq)
    float* rmean = red2 + 256;         // 128
    float* rrstd = rmean + 128;        // 128
    float acc[8][8] = {};
    int bm = blockIdx.x * BM;
    gemm_mainloop(g_z1, B, Bs, As, acc, bm);
    int tid = threadIdx.x;
    int tr = (tid >> 4) * 8;
    int tc = (tid & 15) * 8;
    float bz[8];
#pragma unroll
    for (int j = 0; j < 8; j++) bz[j] = __ldg(&bias[tc + j]);
    __syncthreads();  // done reading Bs — reuse as C tile
    float* Cs = Bs;
#pragma unroll
    for (int i = 0; i < 8; i++) {
        float4 o0, o1;
        o0.x = acc[i][0] + bz[0];
        o0.y = acc[i][1] + bz[1];
        o0.z = acc[i][2] + bz[2];
        o0.w = acc[i][3] + bz[3];
        o1.x = acc[i][4] + bz[4];
        o1.y = acc[i][5] + bz[5];
        o1.z = acc[i][6] + bz[6];
        o1.w = acc[i][7] + bz[7];
        *(float4*)&Cs[(tr + i) * 128 + tc] = o0;
        *(float4*)&Cs[(tr + i) * 128 + tc + 4] = o1;
    }
    __syncthreads();
    // per-row mean/var: 2 threads per row, 64 cols each
    {
        int r = tid >> 1;
        int h0 = (tid & 1) * 64;
        float s = 0.f, s2 = 0.f;
#pragma unroll 8
        for (int c = 0; c < 64; c++) {
            float v = Cs[r * 128 + h0 + c];
            s += v;
            s2 += v * v;
        }
        red[r * 2 + (tid & 1)] = s;
        red2[r * 2 + (tid & 1)] = s2;
    }
    __syncthreads();
    if (tid < 128) {
        float S = red[tid * 2] + red[tid * 2 + 1];
        float S2 = red2[tid * 2] + red2[tid * 2 + 1];
        float mean = S * (1.0f / 128.0f);
        float var = S2 * (1.0f / 128.0f) - mean * mean;
        rmean[tid] = mean;
        rrstd[tid] = rsqrtf(var + LN_EPS);
    }
    __syncthreads();
    // elementwise LN + gelu + residual + hsum (coalesced over tile)
#pragma unroll 4
    for (int i = 0; i < 64; i++) {
        int e = i * 256 + tid;
        int r = e >> 7;
        int c = e & 127;
        int gm = bm + r;
        if (gm < N_NODES) {
            float v = Cs[e];
            v = (v - rmean[r]) * rrstd[r] * __ldg(&lng[c]) + __ldg(&lnb[c]);
            float g = 0.5f * v * (1.0f + erff(v * 0.70710678118654752f));
            size_t gi = (size_t)gm * 128 + c;
            float hn = g + g_h[gi];
            g_h[gi] = hn;
            g_hsum[gi] += hn;
        }
    }
}

// ---------------- final row LayerNorm of g_hsum -> g_z ----------------
__global__ __launch_bounds__(128) void k_rowln(const float* __restrict__ pg,
                                               const float* __restrict__ pb) {
    int r = blockIdx.x;
    int t = threadIdx.x;
    float v = g_hsum[(size_t)r * 128 + t];
    float s = v, s2 = v * v;
#pragma unroll
    for (int o = 16; o > 0; o >>= 1) {
        s += __shfl_down_sync(0xffffffffu, s, o);
        s2 += __shfl_down_sync(0xffffffffu, s2, o);
    }
    __shared__ float aa[4], bb[4];
    int w = t >> 5;
    if ((t & 31) == 0) {
        aa[w] = s;
        bb[w] = s2;
    }
    __syncthreads();
    __shared__ float sm_mean, sm_rstd;
    if (t == 0) {
        float S = aa[0] + aa[1] + aa[2] + aa[3];
        float S2 = bb[0] + bb[1] + bb[2] + bb[3];
        float mean = S * (1.0f / 128.0f);
        float var = S2 * (1.0f / 128.0f) - mean * mean;
        sm_mean = mean;
        sm_rstd = rsqrtf(var + LN_EPS);
    }
    __syncthreads();
    g_z[(size_t)r * 128 + t] = (v - sm_mean) * sm_rstd * __ldg(&pg[t]) + __ldg(&pb[t]);
}

// ---------------- launch ----------------
extern "C" void kernel_launch(void* const* d_in, const int* in_sizes, int n_in,
                              void* d_out, int out_size) {
    const float* x = (const float*)d_in[0];
    const int* edge_index = (const int*)d_in[1];
    const float* W1 = (const float*)d_in[2];
    const float* b1 = (const float*)d_in[3];
    const float* W2 = (const float*)d_in[4];
    const float* b2 = (const float*)d_in[5];
    const float* eps = (const float*)d_in[6];
    const float* ln_g = (const float*)d_in[7];
    const float* ln_b = (const float*)d_in[8];
    const float* pln_g = (const float*)d_in[9];
    const float* pln_b = (const float*)d_in[10];
    const float* pW = (const float*)d_in[11];
    const float* pb = (const float*)d_in[12];
    float* out = (float*)d_out;

    const int* src = edge_index;
    const int* dst = edge_index + N_EDGES;

    const int SMEM = (128 * 128 + 2048 + 256 + 256 + 128 + 128) * 4;  // 76800 B
    cudaFuncSetAttribute(k_gemm_relu, cudaFuncAttributeMaxDynamicSharedMemorySize, SMEM);
    cudaFuncSetAttribute(k_gemm_bias, cudaFuncAttributeMaxDynamicSharedMemorySize, SMEM);
    cudaFuncSetAttribute(k_gemm_ln_gelu_res, cudaFuncAttributeMaxDynamicSharedMemorySize, SMEM);

    // init + CSR build
    k_init<<<(N_NODES * D + 255) / 256, 256>>>(x);
    k_zero_deg<<<(N_NODES + 255) / 256, 256>>>();
    k_hist<<<(N_EDGES + 255) / 256, 256>>>(dst);
    int nblk = (N_NODES + 1023) / 1024;
    k_scan_local<<<nblk, 1024>>>();
    k_scan_top<<<1, 32>>>(nblk);
    k_scan_add<<<(N_NODES + 255) / 256, 256>>>();
    k_scatter<<<(N_EDGES + 255) / 256, 256>>>(src, dst);

    int gblocks = (N_NODES + BM - 1) / BM;  // 782
    for (int i = 0; i < NLAYER; i++) {
        k_agg<<<N_NODES, 128>>>(eps, i);
        k_gemm_relu<<<gblocks, 256, SMEM>>>(W1 + (size_t)i * D * D, b1 + (size_t)i * D);
        k_gemm_ln_gelu_res<<<gblocks, 256, SMEM>>>(W2 + (size_t)i * D * D, b2 + (size_t)i * D,
                                                   ln_g + (size_t)i * D, ln_b + (size_t)i * D);
    }
    k_rowln<<<N_NODES, 128>>>(pln_g, pln_b);
    k_gemm_bias<<<gblocks, 256, SMEM>>>(pW, pb, out);
}